// round 2
// baseline (speedup 1.0000x reference)
#include <cuda_runtime.h>
#include <math.h>

#define NUM_NODES 262144
#define HID 256
#define HH 128
#define NGRAPH 1024

// scratch (static device globals — no allocations allowed)
__device__ float g_s[NUM_NODES];   // scores, then reused for weights
__device__ float g_m[NGRAPH];      // segment max
__device__ float g_sw[NGRAPH];     // segment sum of exp

__device__ __forceinline__ void atomicMaxF(float* addr, float val) {
    // standard float atomic-max via int/uint monotonic mapping
    if (val >= 0.f) atomicMax((int*)addr, __float_as_int(val));
    else            atomicMin((unsigned int*)addr, __float_as_uint(val));
}

__global__ void init_kernel(float* __restrict__ out) {
    int i = blockIdx.x * blockDim.x + threadIdx.x;
    if (i < NGRAPH * HID) out[i] = 0.f;
    if (i < NGRAPH) { g_m[i] = -INFINITY; g_sw[i] = 0.f; }
}

// ---------------------------------------------------------------------------
// score: s[n] = tanh(x[n] @ W1 + b1) @ W2 + b2 ; atomicMax into g_m[batch[n]]
// Block = 128 threads, TILE = 64 nodes. x tile lives in SMEM as float4 rows
// padded to 65 float4 (conflict-free LDS). Two threads split the 128 hidden
// units per node (jh = tid>>6). W1 is read via warp-uniform (broadcast) LDG —
// tiny L1 working set (4 KB per j-block), so no L2 thrash.
// ---------------------------------------------------------------------------
__global__ void __launch_bounds__(128) score_kernel(
    const float* __restrict__ x,
    const int* __restrict__ batch,
    const float* __restrict__ W1,   // [256][128] row-major
    const float* __restrict__ b1,   // [128]
    const float* __restrict__ W2,   // [128]
    const float* __restrict__ b2)   // [1]
{
    extern __shared__ float4 xs[];  // [64][65] float4
    const int tid = threadIdx.x;
    const int base = blockIdx.x * 64;

    const float4* xg = (const float4*)x;
    for (int i = tid; i < 64 * 64; i += 128) {
        int r = i >> 6, c = i & 63;
        xs[r * 65 + c] = xg[(size_t)(base + r) * 64 + c];
    }
    __syncthreads();

    const int nl = tid & 63;        // node within tile
    const int jh = tid >> 6;        // which half of hidden units (0/1)
    const float4* xrow = xs + nl * 65;
    const float4* W1v = (const float4*)W1;   // [256][32] float4
    const float4* b1v = (const float4*)b1;
    const float4* W2v = (const float4*)W2;

    float partial = 0.f;
    for (int jb = jh * 16; jb < jh * 16 + 16; ++jb) {   // jb = j/4
        float4 acc = b1v[jb];
        #pragma unroll 8
        for (int kc = 0; kc < 64; ++kc) {               // k = kc*4
            float4 xa = xrow[kc];
            float4 w0 = W1v[(kc * 4 + 0) * 32 + jb];    // broadcast LDG
            float4 w1 = W1v[(kc * 4 + 1) * 32 + jb];
            float4 w2 = W1v[(kc * 4 + 2) * 32 + jb];
            float4 w3 = W1v[(kc * 4 + 3) * 32 + jb];
            acc.x = fmaf(xa.x, w0.x, acc.x); acc.y = fmaf(xa.x, w0.y, acc.y);
            acc.z = fmaf(xa.x, w0.z, acc.z); acc.w = fmaf(xa.x, w0.w, acc.w);
            acc.x = fmaf(xa.y, w1.x, acc.x); acc.y = fmaf(xa.y, w1.y, acc.y);
            acc.z = fmaf(xa.y, w1.z, acc.z); acc.w = fmaf(xa.y, w1.w, acc.w);
            acc.x = fmaf(xa.z, w2.x, acc.x); acc.y = fmaf(xa.z, w2.y, acc.y);
            acc.z = fmaf(xa.z, w2.z, acc.z); acc.w = fmaf(xa.z, w2.w, acc.w);
            acc.x = fmaf(xa.w, w3.x, acc.x); acc.y = fmaf(xa.w, w3.y, acc.y);
            acc.z = fmaf(xa.w, w3.z, acc.z); acc.w = fmaf(xa.w, w3.w, acc.w);
        }
        float4 wv = W2v[jb];
        partial += tanhf(acc.x) * wv.x + tanhf(acc.y) * wv.y
                 + tanhf(acc.z) * wv.z + tanhf(acc.w) * wv.w;
    }

    __syncthreads();
    float* red = (float*)xs;
    red[tid] = partial;
    __syncthreads();
    if (tid < 64) {
        float s = red[tid] + red[tid + 64] + b2[0];
        int node = base + tid;
        g_s[node] = s;
        atomicMaxF(&g_m[batch[node]], s);
    }
}

// w[n] = exp(s[n] - m[batch[n]]); accumulate segment sums
__global__ void softmax_kernel(const int* __restrict__ batch) {
    int i = blockIdx.x * blockDim.x + threadIdx.x;
    if (i >= NUM_NODES) return;
    int b = batch[i];
    float w = expf(g_s[i] - g_m[b]);
    g_s[i] = w;
    atomicAdd(&g_sw[b], w);
}

// out[b] += x[n] * w[n]/(sw[b]+1e-8). Block = 256 threads (one per feature
// column), 256 nodes per block. batch is sorted, so accumulate in a register
// and flush with atomicAdd only on graph boundaries (~1-2 per block).
__global__ void __launch_bounds__(256) pool_kernel(
    const float* __restrict__ x,
    const int* __restrict__ batch,
    float* __restrict__ out)
{
    const int h = threadIdx.x;
    const int n0 = blockIdx.x * 256;
    int curb = batch[n0];
    float inv = 1.f / (g_sw[curb] + 1e-8f);
    float acc = 0.f;
    for (int n = n0; n < n0 + 256; ++n) {
        int b = batch[n];               // warp-uniform broadcast load
        if (b != curb) {
            atomicAdd(&out[curb * HID + h], acc);
            acc = 0.f;
            curb = b;
            inv = 1.f / (g_sw[b] + 1e-8f);
        }
        acc = fmaf(x[(size_t)n * HID + h], g_s[n] * inv, acc);
    }
    atomicAdd(&out[curb * HID + h], acc);
}

extern "C" void kernel_launch(void* const* d_in, const int* in_sizes, int n_in,
                              void* d_out, int out_size) {
    const float* x     = (const float*)d_in[0];
    const int*   batch = (const int*)d_in[1];
    const float* W1    = (const float*)d_in[2];
    const float* b1    = (const float*)d_in[3];
    const float* W2    = (const float*)d_in[4];
    const float* b2    = (const float*)d_in[5];
    float* out = (float*)d_out;

    const int smem = 64 * 65 * sizeof(float4);   // 66560 B > 48K default
    cudaFuncSetAttribute(score_kernel, cudaFuncAttributeMaxDynamicSharedMemorySize, smem);

    init_kernel<<<(NGRAPH * HID + 255) / 256, 256>>>(out);
    score_kernel<<<NUM_NODES / 64, 128, smem>>>(x, batch, W1, b1, W2, b2);
    softmax_kernel<<<NUM_NODES / 256, 256>>>(batch);
    pool_kernel<<<NUM_NODES / 256, 256>>>(x, batch, out);
}

// round 3
// speedup vs baseline: 5.4215x; 5.4215x over previous
#include <cuda_runtime.h>
#include <math.h>

#define NUM_NODES 262144
#define HID 256
#define HH 128
#define NGRAPH 1024
#define KC 16          // k-chunk for score GEMM

// scratch (static device globals — no allocations allowed)
__device__ float g_s[NUM_NODES];   // scores, then reused for weights
__device__ float g_m[NGRAPH];      // segment max
__device__ float g_sw[NGRAPH];     // segment sum of exp

__device__ __forceinline__ void atomicMaxF(float* addr, float val) {
    if (val >= 0.f) atomicMax((int*)addr, __float_as_int(val));
    else            atomicMin((unsigned int*)addr, __float_as_uint(val));
}

__global__ void init_kernel(float* __restrict__ out) {
    int i = blockIdx.x * blockDim.x + threadIdx.x;
    if (i < NGRAPH * HID) out[i] = 0.f;
    if (i < NGRAPH) { g_m[i] = -INFINITY; g_sw[i] = 0.f; }
}

// ---------------------------------------------------------------------------
// score: register-tiled SGEMM [128 nodes x 128 hidden, K=256] per block,
// 256 threads, 8x8 outputs/thread, double-buffered smem, fused tanh/W2
// epilogue with shfl reduction. s[n] -> g_s, atomicMax into g_m[batch[n]].
// ---------------------------------------------------------------------------
__global__ void __launch_bounds__(256, 2) score_kernel(
    const float* __restrict__ x,
    const int* __restrict__ batch,
    const float* __restrict__ W1,   // [256][128] row-major
    const float* __restrict__ b1,   // [128]
    const float* __restrict__ W2,   // [128]
    const float* __restrict__ b2)   // [1]
{
    __shared__ float xs[2][128][20];   // [buf][node][k] pad 20 -> conflict-free
    __shared__ float ws[2][KC][128];   // [buf][k][j]

    const int tid  = threadIdx.x;
    const int tx   = tid & 15;         // hidden-col group
    const int ty   = tid >> 4;         // node-row group
    const int row0 = ty * 8;
    const int col0 = tx * 8;
    const int base = blockIdx.x * 128;

    const float4* xg = (const float4*)x;   // [node][64]
    const float4* wg = (const float4*)W1;  // [256][32]

    float acc[8][8];
    #pragma unroll
    for (int i = 0; i < 8; ++i)
        #pragma unroll
        for (int j = 0; j < 8; ++j) acc[i][j] = 0.f;

    // ---- load chunk 0 directly into smem buf 0
    #pragma unroll
    for (int j = 0; j < 2; ++j) {
        int i = tid + j * 256;         // 0..511
        int r = i >> 2, kg = i & 3;
        float4 v = xg[(size_t)(base + r) * 64 + kg];
        *(float4*)&xs[0][r][kg * 4] = v;
        int kr = i >> 5, jc = i & 31;
        float4 w = wg[(size_t)kr * 32 + jc];
        *(float4*)&ws[0][kr][jc * 4] = w;
    }
    __syncthreads();

    int buf = 0;
    float4 px[2], pw[2];
    for (int chunk = 0; chunk < 16; ++chunk) {
        // prefetch next chunk into registers
        if (chunk < 15) {
            #pragma unroll
            for (int j = 0; j < 2; ++j) {
                int i = tid + j * 256;
                int r = i >> 2, kg = i & 3;
                px[j] = xg[(size_t)(base + r) * 64 + (chunk + 1) * 4 + kg];
                int kr = i >> 5, jc = i & 31;
                pw[j] = wg[(size_t)((chunk + 1) * KC + kr) * 32 + jc];
            }
        }
        // compute on buf
        #pragma unroll
        for (int k = 0; k < KC; ++k) {
            float xr[8], wr[8];
            #pragma unroll
            for (int i = 0; i < 8; ++i) xr[i] = xs[buf][row0 + i][k];
            *(float4*)&wr[0] = *(float4*)&ws[buf][k][col0];
            *(float4*)&wr[4] = *(float4*)&ws[buf][k][col0 + 4];
            #pragma unroll
            for (int i = 0; i < 8; ++i)
                #pragma unroll
                for (int j = 0; j < 8; ++j)
                    acc[i][j] = fmaf(xr[i], wr[j], acc[i][j]);
        }
        // commit prefetched chunk
        if (chunk < 15) {
            int nb = buf ^ 1;
            #pragma unroll
            for (int j = 0; j < 2; ++j) {
                int i = tid + j * 256;
                int r = i >> 2, kg = i & 3;
                *(float4*)&xs[nb][r][kg * 4] = px[j];
                int kr = i >> 5, jc = i & 31;
                *(float4*)&ws[nb][kr][jc * 4] = pw[j];
            }
            __syncthreads();
            buf = nb;
        }
    }

    // ---- epilogue: s_partial[i] = sum_j tanh(acc+b1)*W2, reduce over tx
    float b1r[8], w2r[8];
    #pragma unroll
    for (int c = 0; c < 8; ++c) {
        b1r[c] = __ldg(&b1[col0 + c]);
        w2r[c] = __ldg(&W2[col0 + c]);
    }
    const float b2v = __ldg(&b2[0]);
    #pragma unroll
    for (int i = 0; i < 8; ++i) {
        float p = 0.f;
        #pragma unroll
        for (int c = 0; c < 8; ++c)
            p += tanhf(acc[i][c] + b1r[c]) * w2r[c];
        p += __shfl_xor_sync(0xFFFFFFFFu, p, 8);
        p += __shfl_xor_sync(0xFFFFFFFFu, p, 4);
        p += __shfl_xor_sync(0xFFFFFFFFu, p, 2);
        p += __shfl_xor_sync(0xFFFFFFFFu, p, 1);
        if (tx == 0) {
            int node = base + row0 + i;
            float s = p + b2v;
            g_s[node] = s;
            atomicMaxF(&g_m[batch[node]], s);
        }
    }
}

// w[n] = exp(s[n] - m[batch[n]]); accumulate segment sums
__global__ void softmax_kernel(const int* __restrict__ batch) {
    int i = blockIdx.x * blockDim.x + threadIdx.x;
    if (i >= NUM_NODES) return;
    int b = batch[i];
    float w = expf(g_s[i] - g_m[b]);
    g_s[i] = w;
    atomicAdd(&g_sw[b], w);
}

// out[b] += x[n] * w[n]/(sw[b]+1e-8). Block = 256 threads: 64 float4 columns
// x 4-node stripes. batch sorted -> register accumulate, flush on boundary.
__global__ void __launch_bounds__(256) pool_kernel(
    const float* __restrict__ x,
    const int* __restrict__ batch,
    float* __restrict__ out)
{
    const int tid = threadIdx.x;
    const int c4  = tid & 63;          // float4 column
    const int r   = tid >> 6;          // node stripe 0..3
    const int n0  = blockIdx.x * 128;
    const float4* x4 = (const float4*)x;   // [node][64]

    float4 acc = make_float4(0.f, 0.f, 0.f, 0.f);
    int curb = batch[n0 + r];
    float inv = __fdividef(1.f, g_sw[curb] + 1e-8f);

    #pragma unroll 8
    for (int n = n0 + r; n < n0 + 128; n += 4) {
        int b = batch[n];
        if (b != curb) {
            float* o = &out[curb * HID + c4 * 4];
            atomicAdd(o + 0, acc.x); atomicAdd(o + 1, acc.y);
            atomicAdd(o + 2, acc.z); atomicAdd(o + 3, acc.w);
            acc = make_float4(0.f, 0.f, 0.f, 0.f);
            curb = b;
            inv = __fdividef(1.f, g_sw[b] + 1e-8f);
        }
        float w = g_s[n] * inv;
        float4 v = x4[(size_t)n * 64 + c4];
        acc.x = fmaf(v.x, w, acc.x); acc.y = fmaf(v.y, w, acc.y);
        acc.z = fmaf(v.z, w, acc.z); acc.w = fmaf(v.w, w, acc.w);
    }
    float* o = &out[curb * HID + c4 * 4];
    atomicAdd(o + 0, acc.x); atomicAdd(o + 1, acc.y);
    atomicAdd(o + 2, acc.z); atomicAdd(o + 3, acc.w);
}

extern "C" void kernel_launch(void* const* d_in, const int* in_sizes, int n_in,
                              void* d_out, int out_size) {
    const float* x     = (const float*)d_in[0];
    const int*   batch = (const int*)d_in[1];
    const float* W1    = (const float*)d_in[2];
    const float* b1    = (const float*)d_in[3];
    const float* W2    = (const float*)d_in[4];
    const float* b2    = (const float*)d_in[5];
    float* out = (float*)d_out;

    init_kernel<<<(NGRAPH * HID + 255) / 256, 256>>>(out);
    score_kernel<<<NUM_NODES / 128, 256>>>(x, batch, W1, b1, W2, b2);
    softmax_kernel<<<NUM_NODES / 256, 256>>>(batch);
    pool_kernel<<<NUM_NODES / 128, 256>>>(x, batch, out);
}

// round 5
// speedup vs baseline: 12.7317x; 2.3484x over previous
#include <cuda_runtime.h>
#include <cuda_bf16.h>
#include <math.h>
#include <stdint.h>

#define NUM_NODES 262144
#define HID 256
#define HH 128
#define NGRAPH 1024
#define NTILES (NUM_NODES / 128)   // 2048
#define NSM 148

// ---------------- scratch (static device globals) ----------------
__device__ float g_s[NUM_NODES];   // scores, then weights
__device__ float g_m[NGRAPH];      // segment max
__device__ float g_sw[NGRAPH];     // segment sum of exp
// W1^T as b-fragment u32 pairs: [split][n=128][132 u32(pad)] ; kp = k/2
#define BROW 132
#define BSPLIT (128 * BROW)        // 16896 u32
__device__ uint32_t g_B[2 * BSPLIT];

__device__ __forceinline__ void atomicMaxF(float* addr, float val) {
    if (val >= 0.f) atomicMax((int*)addr, __float_as_int(val));
    else            atomicMin((unsigned int*)addr, __float_as_uint(val));
}

__device__ __forceinline__ void mma_bf16(float* c, const uint32_t* a,
                                         uint32_t b0, uint32_t b1) {
    asm volatile(
        "mma.sync.aligned.m16n8k16.row.col.f32.bf16.bf16.f32 "
        "{%0,%1,%2,%3}, {%4,%5,%6,%7}, {%8,%9}, {%0,%1,%2,%3};"
        : "+f"(c[0]), "+f"(c[1]), "+f"(c[2]), "+f"(c[3])
        : "r"(a[0]), "r"(a[1]), "r"(a[2]), "r"(a[3]), "r"(b0), "r"(b1));
}

// ---------------- prep: W1^T -> split bf16 u32 pairs ----------------
__global__ void prep_kernel(const float* __restrict__ W1) {  // W1[256][128]
    int i = blockIdx.x * 256 + threadIdx.x;   // 0..16383
    if (i >= 16384) return;
    int n = i >> 7, kp = i & 127;
    float w0 = W1[(2 * kp) * 128 + n];
    float w1 = W1[(2 * kp + 1) * 128 + n];
    __nv_bfloat16 h0 = __float2bfloat16(w0), h1 = __float2bfloat16(w1);
    float l0f = w0 - __bfloat162float(h0), l1f = w1 - __bfloat162float(h1);
    __nv_bfloat16 l0 = __float2bfloat16(l0f), l1 = __float2bfloat16(l1f);
    uint32_t hv = (uint32_t)*(unsigned short*)&h0 | ((uint32_t)*(unsigned short*)&h1 << 16);
    uint32_t lv = (uint32_t)*(unsigned short*)&l0 | ((uint32_t)*(unsigned short*)&l1 << 16);
    g_B[0 * BSPLIT + n * BROW + kp] = hv;
    g_B[1 * BSPLIT + n * BROW + kp] = lv;
}

__global__ void init_kernel(float* __restrict__ out) {
    int i = blockIdx.x * blockDim.x + threadIdx.x;
    if (i < NGRAPH * HID) out[i] = 0.f;
    if (i < NGRAPH) { g_m[i] = -INFINITY; g_sw[i] = 0.f; }
}

// ---------------------------------------------------------------------------
// score: persistent CTAs, HMMA bf16-split GEMM [128 x 128, K=256] per tile.
// 8 warps/CTA, warp w owns rows w*16..w*16+15. B resident in smem, A staged
// per-warp per 64-k chunk (hi+lo). Fused tanh*W2 epilogue.
// dyn smem u32 layout: B[0 .. 33792) ; A slabs: warp w at 33792 + w*1152,
//   hi [16][36], lo at +576.
// ---------------------------------------------------------------------------
#define A_OFF 33792
#define A_WSZ 1152
#define A_PAD 36

__global__ void __launch_bounds__(256, 1) score_kernel(
    const float* __restrict__ x,
    const int* __restrict__ batch,
    const float* __restrict__ b1,
    const float* __restrict__ W2,
    const float* __restrict__ b2)
{
    extern __shared__ uint32_t sm[];
    __shared__ float sb1[128], sW2[128];

    const int tid = threadIdx.x, w = tid >> 5, l = tid & 31;
    const int gr = l >> 2, qc = l & 3;            // frag row / col-quad

    // B copy: 33792 u32 = 8448 float4
    {
        const float4* src = (const float4*)g_B;
        float4* dst = (float4*)sm;
        for (int i = tid; i < 8448; i += 256) dst[i] = src[i];
    }
    if (tid < 128) { sb1[tid] = b1[tid]; sW2[tid] = W2[tid]; }
    __syncthreads();

    const float b2v = __ldg(&b2[0]);
    uint32_t* const Ahi = sm + A_OFF + w * A_WSZ;
    uint32_t* const Alo = Ahi + 576;
    const float4* xg = (const float4*)x;          // [node][64]

    for (int t = blockIdx.x; t < NTILES; t += NSM) {
        const int base = t * 128;
        const int rbase = base + w * 16;

        float acc[16][4];
        #pragma unroll
        for (int nt = 0; nt < 16; ++nt)
            #pragma unroll
            for (int j = 0; j < 4; ++j) acc[nt][j] = 0.f;

        // prefetch chunk 0: 8 float4/lane; f = i*32+l: row f/16, col4 f%16
        float4 v[8];
        #pragma unroll
        for (int i = 0; i < 8; ++i) {
            int f = i * 32 + l;
            v[i] = xg[(size_t)(rbase + (f >> 4)) * 64 + (f & 15)];
        }

        for (int c = 0; c < 4; ++c) {
            __syncwarp();
            // store chunk c (hi/lo) into warp slab
            #pragma unroll
            for (int i = 0; i < 8; ++i) {
                int f = i * 32 + l;
                int r = f >> 4, q = f & 15;       // q: float4 within 64-col chunk
                __nv_bfloat162 h01 = __float22bfloat162_rn(make_float2(v[i].x, v[i].y));
                __nv_bfloat162 h23 = __float22bfloat162_rn(make_float2(v[i].z, v[i].w));
                float2 f01 = __bfloat1622float2(h01);
                float2 f23 = __bfloat1622float2(h23);
                __nv_bfloat162 l01 = __float22bfloat162_rn(make_float2(v[i].x - f01.x, v[i].y - f01.y));
                __nv_bfloat162 l23 = __float22bfloat162_rn(make_float2(v[i].z - f23.x, v[i].w - f23.y));
                Ahi[r * A_PAD + q * 2]     = *(uint32_t*)&h01;
                Ahi[r * A_PAD + q * 2 + 1] = *(uint32_t*)&h23;
                Alo[r * A_PAD + q * 2]     = *(uint32_t*)&l01;
                Alo[r * A_PAD + q * 2 + 1] = *(uint32_t*)&l23;
            }
            __syncwarp();
            // prefetch chunk c+1 while MMAs run
            if (c < 3) {
                #pragma unroll
                for (int i = 0; i < 8; ++i) {
                    int f = i * 32 + l;
                    v[i] = xg[(size_t)(rbase + (f >> 4)) * 64 + (c + 1) * 16 + (f & 15)];
                }
            }
            for (int k16 = 0; k16 < 4; ++k16) {
                uint32_t ah[4], al[4];
                int ab = k16 * 8 + qc;
                ah[0] = Ahi[gr * A_PAD + ab];       ah[1] = Ahi[(gr + 8) * A_PAD + ab];
                ah[2] = Ahi[gr * A_PAD + ab + 4];   ah[3] = Ahi[(gr + 8) * A_PAD + ab + 4];
                al[0] = Alo[gr * A_PAD + ab];       al[1] = Alo[(gr + 8) * A_PAD + ab];
                al[2] = Alo[gr * A_PAD + ab + 4];   al[3] = Alo[(gr + 8) * A_PAD + ab + 4];
                const int kp = c * 32 + k16 * 8 + qc;
                #pragma unroll
                for (int nt = 0; nt < 16; ++nt) {
                    const uint32_t* Bh = sm + (nt * 8 + gr) * BROW + kp;
                    const uint32_t* Bl = Bh + BSPLIT;
                    uint32_t bh0 = Bh[0], bh1 = Bh[4];
                    uint32_t bl0 = Bl[0], bl1 = Bl[4];
                    mma_bf16(acc[nt], ah, bh0, bh1);
                    mma_bf16(acc[nt], ah, bl0, bl1);
                    mma_bf16(acc[nt], al, bh0, bh1);
                }
            }
        }

        // epilogue: p0 = row gr, p1 = row gr+8
        float p0 = 0.f, p1 = 0.f;
        #pragma unroll
        for (int nt = 0; nt < 16; ++nt) {
            #pragma unroll
            for (int j = 0; j < 2; ++j) {
                int col = nt * 8 + qc * 2 + j;
                float bb = sb1[col], ww = sW2[col];
                float h0 = acc[nt][j] + bb;
                float e0 = __expf(2.f * h0);
                p0 = fmaf(1.f - __fdividef(2.f, e0 + 1.f), ww, p0);
                float h1 = acc[nt][2 + j] + bb;
                float e1 = __expf(2.f * h1);
                p1 = fmaf(1.f - __fdividef(2.f, e1 + 1.f), ww, p1);
            }
        }
        p0 += __shfl_xor_sync(0xFFFFFFFFu, p0, 1);
        p0 += __shfl_xor_sync(0xFFFFFFFFu, p0, 2);
        p1 += __shfl_xor_sync(0xFFFFFFFFu, p1, 1);
        p1 += __shfl_xor_sync(0xFFFFFFFFu, p1, 2);
        if (qc == 0) {
            int n0 = rbase + gr;
            float s0 = p0 + b2v;
            g_s[n0] = s0;
            atomicMaxF(&g_m[batch[n0]], s0);
            int n1 = n0 + 8;
            float s1 = p1 + b2v;
            g_s[n1] = s1;
            atomicMaxF(&g_m[batch[n1]], s1);
        }
    }
}

// ---------------- softmax ----------------
__global__ void softmax_kernel(const int* __restrict__ batch) {
    int i = blockIdx.x * blockDim.x + threadIdx.x;
    if (i >= NUM_NODES) return;
    int b = batch[i];
    float w = expf(g_s[i] - g_m[b]);
    g_s[i] = w;
    atomicAdd(&g_sw[b], w);
}

// ---------------- pool ----------------
__global__ void __launch_bounds__(256) pool_kernel(
    const float* __restrict__ x,
    const int* __restrict__ batch,
    float* __restrict__ out)
{
    const int tid = threadIdx.x;
    const int c4  = tid & 63;
    const int r   = tid >> 6;
    const int n0  = blockIdx.x * 128;
    const float4* x4 = (const float4*)x;

    float4 acc = make_float4(0.f, 0.f, 0.f, 0.f);
    int curb = batch[n0 + r];
    float inv = __fdividef(1.f, g_sw[curb] + 1e-8f);

    #pragma unroll 8
    for (int n = n0 + r; n < n0 + 128; n += 4) {
        int b = batch[n];
        if (b != curb) {
            float* o = &out[curb * HID + c4 * 4];
            atomicAdd(o + 0, acc.x); atomicAdd(o + 1, acc.y);
            atomicAdd(o + 2, acc.z); atomicAdd(o + 3, acc.w);
            acc = make_float4(0.f, 0.f, 0.f, 0.f);
            curb = b;
            inv = __fdividef(1.f, g_sw[b] + 1e-8f);
        }
        float w = g_s[n] * inv;
        float4 vv = x4[(size_t)n * 64 + c4];
        acc.x = fmaf(vv.x, w, acc.x); acc.y = fmaf(vv.y, w, acc.y);
        acc.z = fmaf(vv.z, w, acc.z); acc.w = fmaf(vv.w, w, acc.w);
    }
    float* o = &out[curb * HID + c4 * 4];
    atomicAdd(o + 0, acc.x); atomicAdd(o + 1, acc.y);
    atomicAdd(o + 2, acc.z); atomicAdd(o + 3, acc.w);
}

extern "C" void kernel_launch(void* const* d_in, const int* in_sizes, int n_in,
                              void* d_out, int out_size) {
    const float* x     = (const float*)d_in[0];
    const int*   batch = (const int*)d_in[1];
    const float* W1    = (const float*)d_in[2];
    const float* b1    = (const float*)d_in[3];
    const float* W2    = (const float*)d_in[4];
    const float* b2    = (const float*)d_in[5];
    float* out = (float*)d_out;

    const int dyn = (A_OFF + 8 * A_WSZ) * 4;   // 135168 + 36864 = 172032 B
    cudaFuncSetAttribute(score_kernel, cudaFuncAttributeMaxDynamicSharedMemorySize, dyn);

    prep_kernel<<<64, 256>>>(W1);
    init_kernel<<<(NGRAPH * HID + 255) / 256, 256>>>(out);
    score_kernel<<<NSM, 256, dyn>>>(x, batch, b1, W2, b2);
    softmax_kernel<<<NUM_NODES / 256, 256>>>(batch);
    pool_kernel<<<NUM_NODES / 128, 256>>>(x, batch, out);
}